// round 3
// baseline (speedup 1.0000x reference)
#include <cuda_runtime.h>

// Problem dims (compile-time, from reference)
#define BDIM 2
#define CDIM 3
#define DDIM 128
#define HDIM 192
#define WDIM 192

// ---------------------------------------------------------------------------
// X pass: solve along W (contiguous). Shared-memory tile, one thread per line.
// ---------------------------------------------------------------------------
constexpr int LINES_X = 128;             // lines per block == blockDim.x
constexpr int PADW    = 193;             // 193 % 32 == 1 -> conflict-free columns
constexpr int SMEM_X  = (LINES_X * PADW + 3 * WDIM) * (int)sizeof(float);

__global__ __launch_bounds__(LINES_X) void solve_x_kernel(
    const float* __restrict__ in, float* __restrict__ out,
    const float* __restrict__ a, const float* __restrict__ b,
    const float* __restrict__ c)
{
    extern __shared__ float smem[];
    float* tile   = smem;                       // [LINES_X][PADW]
    float* s_inva = smem + LINES_X * PADW;      // [WDIM]
    float* s_b    = s_inva + WDIM;              // [WDIM-1] (padded)
    float* s_c    = s_b + WDIM;                 // [WDIM-1] (padded)

    const int t = threadIdx.x;

    // coefficients
    for (int i = t; i < WDIM; i += LINES_X) {
        s_inva[i] = 1.0f / a[i];
        if (i < WDIM - 1) { s_b[i] = b[i]; s_c[i] = c[i]; }
    }

    // coalesced tile load
    const size_t base = (size_t)blockIdx.x * (LINES_X * WDIM);
    #pragma unroll 4
    for (int idx = t; idx < LINES_X * WDIM; idx += LINES_X) {
        tile[(idx / WDIM) * PADW + (idx % WDIM)] = in[base + idx];
    }
    __syncthreads();

    // per-thread Thomas solve in smem
    float* ln = tile + t * PADW;
    float carry = ln[0];
    #pragma unroll 8
    for (int i = 1; i < WDIM; i++) {
        carry = fmaf(-s_c[i - 1], carry, ln[i]);
        ln[i] = carry;
    }
    carry = carry * s_inva[WDIM - 1];
    ln[WDIM - 1] = carry;
    #pragma unroll 8
    for (int i = WDIM - 2; i >= 0; i--) {
        carry = fmaf(-s_b[i], carry, ln[i]) * s_inva[i];
        ln[i] = carry;
    }
    __syncthreads();

    // coalesced store
    #pragma unroll 4
    for (int idx = t; idx < LINES_X * WDIM; idx += LINES_X) {
        out[base + idx] = tile[(idx / WDIM) * PADW + (idx % WDIM)];
    }
}

// ---------------------------------------------------------------------------
// Strided passes (Y: stride W, Z: stride H*W). One thread per line, in-place
// two-sweep Thomas; forward intermediates live in d_out, backward reads them
// back (expected L2 hits). STRIDE compile-time so the compiler can
// disambiguate in-place read/write and keep MLP across the unroll.
// ---------------------------------------------------------------------------
template <int N, int STRIDE>
__device__ __forceinline__ void solve_line_strided(
    float* __restrict__ p,
    const float* __restrict__ s_inva,
    const float* __restrict__ s_b,
    const float* __restrict__ s_c)
{
    float carry = p[0];
    #pragma unroll 8
    for (int i = 1; i < N; i++) {
        carry = fmaf(-s_c[i - 1], carry, p[(size_t)i * STRIDE]);
        p[(size_t)i * STRIDE] = carry;
    }
    carry = carry * s_inva[N - 1];
    p[(size_t)(N - 1) * STRIDE] = carry;
    #pragma unroll 8
    for (int i = N - 2; i >= 0; i--) {
        carry = fmaf(-s_b[i], carry, p[(size_t)i * STRIDE]) * s_inva[i];
        p[(size_t)i * STRIDE] = carry;
    }
}

constexpr int TPB_S = 256;

__global__ __launch_bounds__(TPB_S) void solve_y_kernel(
    float* __restrict__ data,
    const float* __restrict__ a, const float* __restrict__ b,
    const float* __restrict__ c)
{
    __shared__ float s_inva[HDIM], s_b[HDIM], s_c[HDIM];
    const int t = threadIdx.x;
    for (int i = t; i < HDIM; i += TPB_S) {
        s_inva[i] = 1.0f / a[i];
        if (i < HDIM - 1) { s_b[i] = b[i]; s_c[i] = c[i]; }
    }
    __syncthreads();

    const int L   = blockIdx.x * TPB_S + t;      // line id over (b,c,d) x w
    const int bcd = L / WDIM;                    // constant divisor -> mul.hi
    const int w   = L - bcd * WDIM;
    float* p = data + (size_t)bcd * (HDIM * WDIM) + w;
    solve_line_strided<HDIM, WDIM>(p, s_inva, s_b, s_c);
}

__global__ __launch_bounds__(TPB_S) void solve_z_kernel(
    float* __restrict__ data,
    const float* __restrict__ a, const float* __restrict__ b,
    const float* __restrict__ c)
{
    __shared__ float s_inva[DDIM], s_b[DDIM], s_c[DDIM];
    const int t = threadIdx.x;
    for (int i = t; i < DDIM; i += TPB_S) {
        s_inva[i] = 1.0f / a[i];
        if (i < DDIM - 1) { s_b[i] = b[i]; s_c[i] = c[i]; }
    }
    __syncthreads();

    const int L  = blockIdx.x * TPB_S + t;       // line id over (b,c) x (h,w)
    const int bc = L / (HDIM * WDIM);
    const int hw = L - bc * (HDIM * WDIM);
    float* p = data + (size_t)bc * (DDIM * HDIM * WDIM) + hw;
    solve_line_strided<DDIM, HDIM * WDIM>(p, s_inva, s_b, s_c);
}

// ---------------------------------------------------------------------------
// Launch
// ---------------------------------------------------------------------------
extern "C" void kernel_launch(void* const* d_in, const int* in_sizes, int n_in,
                              void* d_out, int out_size)
{
    const float* field = (const float*)d_in[0];
    const float* ax = (const float*)d_in[1];
    const float* bx = (const float*)d_in[2];
    const float* cx = (const float*)d_in[3];
    const float* ay = (const float*)d_in[4];
    const float* by = (const float*)d_in[5];
    const float* cy = (const float*)d_in[6];
    const float* az = (const float*)d_in[7];
    const float* bz = (const float*)d_in[8];
    const float* cz = (const float*)d_in[9];
    float* out = (float*)d_out;

    (void)in_sizes; (void)n_in; (void)out_size;

    // Opt-in to >48KB dynamic smem for the X kernel. This API enqueues no
    // work, so it is graph-capture-safe; it is also idempotent across calls.
    cudaFuncSetAttribute(solve_x_kernel,
                         cudaFuncAttributeMaxDynamicSharedMemorySize, SMEM_X);

    // X pass: lines over (b,c,d,h) = 2*3*128*192 = 147456 lines / 128 = 1152 blocks
    const int lines_x = BDIM * CDIM * DDIM * HDIM;
    solve_x_kernel<<<lines_x / LINES_X, LINES_X, SMEM_X>>>(field, out, ax, bx, cx);

    // Y pass: lines over (b,c,d,w) = 147456 / 256 = 576 blocks
    const int lines_y = BDIM * CDIM * DDIM * WDIM;
    solve_y_kernel<<<lines_y / TPB_S, TPB_S>>>(out, ay, by, cy);

    // Z pass: lines over (b,c,h,w) = 2*3*192*192 = 221184 / 256 = 864 blocks
    const int lines_z = BDIM * CDIM * HDIM * WDIM;
    solve_z_kernel<<<lines_z / TPB_S, TPB_S>>>(out, az, bz, cz);
}

// round 4
// speedup vs baseline: 1.4518x; 1.4518x over previous
#include <cuda_runtime.h>

// Problem dims (compile-time, from reference)
#define BDIM 2
#define CDIM 3
#define DDIM 128
#define HDIM 192
#define WDIM 192

// ---------------------------------------------------------------------------
// X pass: solve along W (contiguous). Warp-local 32x33 transpose tiles,
// 6 chunks of 32 columns; y intermediates round-trip through `out` (L2),
// last chunk kept in registers. 8 warps/block, 36KB smem -> ~75% occupancy.
// ---------------------------------------------------------------------------
constexpr int XWARPS = 8;
constexpr int XTPB   = XWARPS * 32;

__global__ __launch_bounds__(XTPB) void solve_x_kernel(
    const float* __restrict__ in, float* __restrict__ out,
    const float* __restrict__ a, const float* __restrict__ b,
    const float* __restrict__ c)
{
    __shared__ float tile[XWARPS][32][33];
    __shared__ float s_inva[WDIM], s_b[WDIM], s_c[WDIM];

    const int t    = threadIdx.x;
    const int wid  = t >> 5;
    const int lane = t & 31;

    for (int i = t; i < WDIM; i += XTPB) {
        s_inva[i] = 1.0f / a[i];
        if (i < WDIM - 1) { s_b[i] = b[i]; s_c[i] = c[i]; }
    }
    __syncthreads();

    float (*tl)[33] = tile[wid];
    const int line0 = (blockIdx.x * XWARPS + wid) * 32;
    const int r0 = lane >> 3;          // 0..3
    const int cm = (lane & 7) * 4;     // 0,4,...,28

    float carry = 0.0f;
    float yreg[32];

    // ---------------- forward sweep ----------------
    for (int k = 0; k < 6; k++) {
        const int c0 = k * 32;
        // coalesced float4 load -> transpose tile (conflict-free scalar STS)
        #pragma unroll
        for (int rr = 0; rr < 32; rr += 4) {
            const int r = rr + r0;
            float4 v = *(const float4*)(in + (size_t)(line0 + r) * WDIM + c0 + cm);
            tl[r][cm]     = v.x; tl[r][cm + 1] = v.y;
            tl[r][cm + 2] = v.z; tl[r][cm + 3] = v.w;
        }
        __syncwarp();
        // lane solves its own row (stride-33 -> conflict-free)
        #pragma unroll
        for (int j = 0; j < 32; j++) {
            const float x = tl[lane][j];
            const int i = c0 + j;
            carry = (i == 0) ? x : fmaf(-s_c[i - 1], carry, x);
            yreg[j] = carry;
        }
        if (k < 5) {  // last chunk stays in registers for the backward sweep
            #pragma unroll
            for (int j = 0; j < 32; j++) tl[lane][j] = yreg[j];
            __syncwarp();
            #pragma unroll
            for (int rr = 0; rr < 32; rr += 4) {
                const int r = rr + r0;
                float4 v = make_float4(tl[r][cm], tl[r][cm + 1],
                                       tl[r][cm + 2], tl[r][cm + 3]);
                *(float4*)(out + (size_t)(line0 + r) * WDIM + c0 + cm) = v;
            }
        }
        __syncwarp();
    }

    // ---------------- backward sweep ----------------
    // chunk 5 directly from registers
    {
        const int c0 = 5 * 32;
        #pragma unroll
        for (int j = 31; j >= 0; j--) {
            const int i = c0 + j;
            const float x = yreg[j];
            carry = (i == WDIM - 1) ? x * s_inva[i]
                                    : fmaf(-s_b[i], carry, x) * s_inva[i];
            yreg[j] = carry;
        }
        #pragma unroll
        for (int j = 0; j < 32; j++) tl[lane][j] = yreg[j];
        __syncwarp();
        #pragma unroll
        for (int rr = 0; rr < 32; rr += 4) {
            const int r = rr + r0;
            float4 v = make_float4(tl[r][cm], tl[r][cm + 1],
                                   tl[r][cm + 2], tl[r][cm + 3]);
            *(float4*)(out + (size_t)(line0 + r) * WDIM + c0 + cm) = v;
        }
        __syncwarp();
    }
    // chunks 4..0: reload y from out (same lane wrote these addresses -> coherent)
    for (int k = 4; k >= 0; k--) {
        const int c0 = k * 32;
        #pragma unroll
        for (int rr = 0; rr < 32; rr += 4) {
            const int r = rr + r0;
            float4 v = *(const float4*)(out + (size_t)(line0 + r) * WDIM + c0 + cm);
            tl[r][cm]     = v.x; tl[r][cm + 1] = v.y;
            tl[r][cm + 2] = v.z; tl[r][cm + 3] = v.w;
        }
        __syncwarp();
        #pragma unroll
        for (int j = 31; j >= 0; j--) {
            const int i = c0 + j;
            const float x = tl[lane][j];
            carry = fmaf(-s_b[i], carry, x) * s_inva[i];   // i < 191 always here
            yreg[j] = carry;
        }
        #pragma unroll
        for (int j = 0; j < 32; j++) tl[lane][j] = yreg[j];
        __syncwarp();
        #pragma unroll
        for (int rr = 0; rr < 32; rr += 4) {
            const int r = rr + r0;
            float4 v = make_float4(tl[r][cm], tl[r][cm + 1],
                                   tl[r][cm + 2], tl[r][cm + 3]);
            *(float4*)(out + (size_t)(line0 + r) * WDIM + c0 + cm) = v;
        }
        __syncwarp();
    }
}

// ---------------------------------------------------------------------------
// Strided passes (Y: stride W, Z: stride H*W), float2-vectorized over w.
// In-place two-sweep Thomas; forward intermediates live in d_out, backward
// reads come back from L2.
// ---------------------------------------------------------------------------
template <int N, int S2>   // S2 = stride in float2 units
__device__ __forceinline__ void solve_line2(
    float2* __restrict__ p,
    const float* __restrict__ s_inva,
    const float* __restrict__ s_b,
    const float* __restrict__ s_c)
{
    float2 carry = p[0];
    #pragma unroll 8
    for (int i = 1; i < N; i++) {
        const float2 x = p[(size_t)i * S2];
        const float ci = s_c[i - 1];
        carry.x = fmaf(-ci, carry.x, x.x);
        carry.y = fmaf(-ci, carry.y, x.y);
        p[(size_t)i * S2] = carry;
    }
    const float ian = s_inva[N - 1];
    carry.x *= ian; carry.y *= ian;
    p[(size_t)(N - 1) * S2] = carry;
    #pragma unroll 8
    for (int i = N - 2; i >= 0; i--) {
        const float2 y = p[(size_t)i * S2];
        const float bi = s_b[i], iai = s_inva[i];
        carry.x = fmaf(-bi, carry.x, y.x) * iai;
        carry.y = fmaf(-bi, carry.y, y.y) * iai;
        p[(size_t)i * S2] = carry;
    }
}

constexpr int TPB_S = 256;

__global__ __launch_bounds__(TPB_S) void solve_y_kernel(
    float* __restrict__ data,
    const float* __restrict__ a, const float* __restrict__ b,
    const float* __restrict__ c)
{
    __shared__ float s_inva[HDIM], s_b[HDIM], s_c[HDIM];
    const int t = threadIdx.x;
    for (int i = t; i < HDIM; i += TPB_S) {
        s_inva[i] = 1.0f / a[i];
        if (i < HDIM - 1) { s_b[i] = b[i]; s_c[i] = c[i]; }
    }
    __syncthreads();

    const int L   = blockIdx.x * TPB_S + t;      // float2-line over (b,c,d) x w2
    const int bcd = L / (WDIM / 2);
    const int w2  = L - bcd * (WDIM / 2);
    float2* p = (float2*)data + (size_t)bcd * (HDIM * WDIM / 2) + w2;
    solve_line2<HDIM, WDIM / 2>(p, s_inva, s_b, s_c);
}

__global__ __launch_bounds__(TPB_S) void solve_z_kernel(
    float* __restrict__ data,
    const float* __restrict__ a, const float* __restrict__ b,
    const float* __restrict__ c)
{
    __shared__ float s_inva[DDIM], s_b[DDIM], s_c[DDIM];
    const int t = threadIdx.x;
    for (int i = t; i < DDIM; i += TPB_S) {
        s_inva[i] = 1.0f / a[i];
        if (i < DDIM - 1) { s_b[i] = b[i]; s_c[i] = c[i]; }
    }
    __syncthreads();

    const int L   = blockIdx.x * TPB_S + t;      // float2-line over (b,c) x (h,w2)
    const int bc  = L / (HDIM * WDIM / 2);
    const int hw2 = L - bc * (HDIM * WDIM / 2);
    float2* p = (float2*)data + (size_t)bc * (DDIM * HDIM * WDIM / 2) + hw2;
    solve_line2<DDIM, HDIM * WDIM / 2>(p, s_inva, s_b, s_c);
}

// ---------------------------------------------------------------------------
// Launch
// ---------------------------------------------------------------------------
extern "C" void kernel_launch(void* const* d_in, const int* in_sizes, int n_in,
                              void* d_out, int out_size)
{
    const float* field = (const float*)d_in[0];
    const float* ax = (const float*)d_in[1];
    const float* bx = (const float*)d_in[2];
    const float* cx = (const float*)d_in[3];
    const float* ay = (const float*)d_in[4];
    const float* by = (const float*)d_in[5];
    const float* cy = (const float*)d_in[6];
    const float* az = (const float*)d_in[7];
    const float* bz = (const float*)d_in[8];
    const float* cz = (const float*)d_in[9];
    float* out = (float*)d_out;

    (void)in_sizes; (void)n_in; (void)out_size;

    // X pass: 147456 lines / (8 warps * 32 lines) = 576 blocks
    const int lines_x = BDIM * CDIM * DDIM * HDIM;
    solve_x_kernel<<<lines_x / (XWARPS * 32), XTPB>>>(field, out, ax, bx, cx);

    // Y pass: float2 lines = 2*3*128*96 = 73728 / 256 = 288 blocks
    const int l2_y = BDIM * CDIM * DDIM * (WDIM / 2);
    solve_y_kernel<<<l2_y / TPB_S, TPB_S>>>(out, ay, by, cy);

    // Z pass: float2 lines = 2*3*192*96 = 110592 / 256 = 432 blocks
    const int l2_z = BDIM * CDIM * HDIM * (WDIM / 2);
    solve_z_kernel<<<l2_z / TPB_S, TPB_S>>>(out, az, bz, cz);
}